// round 11
// baseline (speedup 1.0000x reference)
#include <cuda_runtime.h>
#include <cuda_bf16.h>

// Problem constants
#define BB   2
#define NN_  4096
#define NQv  1024
#define DIMv 512
#define HH   8
#define DHv  64
#define LMv  256
#define BHv  16
#define INNER 512

typedef unsigned long long u64;

// ---------------- f32x2 packed helpers (Blackwell) ----------------
__device__ __forceinline__ void ffma2(u64 &d, u64 a, u64 b) {
    asm("fma.rn.f32x2 %0, %1, %2, %0;" : "+l"(d) : "l"(a), "l"(b));
}
__device__ __forceinline__ u64 pack2(float x, float y) {
    u64 r; asm("mov.b64 %0, {%1, %2};" : "=l"(r) : "f"(x), "f"(y)); return r;
}
__device__ __forceinline__ u64 dup2(float x) { return pack2(x, x); }
__device__ __forceinline__ float2 unpack2(u64 v) {
    float lo, hi; asm("mov.b64 {%0, %1}, %2;" : "=f"(lo), "=f"(hi) : "l"(v));
    return make_float2(lo, hi);
}
__device__ __forceinline__ void fmul2(u64 &d, u64 a) {
    asm("mul.rn.f32x2 %0, %0, %1;" : "+l"(d) : "l"(a));
}

// ---------------- scratch (device globals; no allocation allowed) ----------------
__device__ float g_kv[(long)BB*NN_*1024];
__device__ float g_qmat[(long)BB*NQv*INNER];
__device__ float g_klT[BHv*DHv*LMv];           // landmarks TRANSPOSED (bh, 64, 256)
__device__ float g_attn1[(long)BHv*NQv*LMv];
__device__ float g_G[BHv*LMv*LMv];
__device__ float g_qA[BHv*LMv*LMv];
__device__ float g_qB[BHv*LMv*LMv];
__device__ float g_M[BHv*LMv*LMv];
__device__ float g_r1[BHv*LMv*LMv];
__device__ float g_r2[BHv*LMv*LMv];
__device__ float g_Y[BHv*NQv*DHv];
__device__ float g_xty[BHv*LMv*DHv];
__device__ float g_z2[BHv*LMv*DHv];
__device__ float g_oc[(long)BB*NQv*INNER];
__device__ float g_max[1];

// ---------------- 128x128 SGEMM, f32x2 accumulators (big contiguous GEMMs) -------
__global__ __launch_bounds__(256) void sgemm128_kernel(
    const float* __restrict__ A, const float* __restrict__ B,
    const float* __restrict__ bias, float* __restrict__ C,
    int M, int N, int K, float alpha)
{
    __shared__ float As[2][8][132];
    __shared__ float Bs[2][8][128];

    int tid = threadIdx.x;
    int ty = tid >> 4, tx = tid & 15;
    int i0 = blockIdx.y * 128, j0 = blockIdx.x * 128;

    int arow = tid >> 1, akq = (tid & 1) * 4;
    int bkr = tid >> 5, bcq = (tid & 31) * 4;

    const float* Aptr = A + (long)(i0 + arow) * K + akq;
    const float* Bptr = B + (long)bkr * N + j0 + bcq;

    float4 av = *(const float4*)Aptr;
    float4 bv = *(const float4*)Bptr;
    As[0][akq + 0][arow] = av.x; As[0][akq + 1][arow] = av.y;
    As[0][akq + 2][arow] = av.z; As[0][akq + 3][arow] = av.w;
    *(float4*)&Bs[0][bkr][bcq] = bv;
    __syncthreads();

    u64 acc2[4][8] = {};
    int T = K / 8;
    int buf = 0;
    for (int t = 0; t < T; t++) {
        if (t + 1 < T) {
            av = *(const float4*)(Aptr + (t + 1) * 8);
            bv = *(const float4*)(Bptr + (long)(t + 1) * 8 * N);
        }
        #pragma unroll
        for (int kk = 0; kk < 8; kk++) {
            ulonglong2 a01 = *(const ulonglong2*)&As[buf][kk][ty * 8];
            ulonglong2 a23 = *(const ulonglong2*)&As[buf][kk][ty * 8 + 4];
            float4 b0 = *(const float4*)&Bs[buf][kk][tx * 8];
            float4 b1 = *(const float4*)&Bs[buf][kk][tx * 8 + 4];
            u64 ap[4] = {a01.x, a01.y, a23.x, a23.y};
            u64 bd[8] = {dup2(b0.x), dup2(b0.y), dup2(b0.z), dup2(b0.w),
                         dup2(b1.x), dup2(b1.y), dup2(b1.z), dup2(b1.w)};
            #pragma unroll
            for (int p = 0; p < 4; p++)
                #pragma unroll
                for (int j = 0; j < 8; j++)
                    ffma2(acc2[p][j], ap[p], bd[j]);
        }
        if (t + 1 < T) {
            int nb = buf ^ 1;
            As[nb][akq + 0][arow] = av.x; As[nb][akq + 1][arow] = av.y;
            As[nb][akq + 2][arow] = av.z; As[nb][akq + 3][arow] = av.w;
            *(float4*)&Bs[nb][bkr][bcq] = bv;
            __syncthreads();
            buf = nb;
        }
    }

    #pragma unroll
    for (int p = 0; p < 4; p++) {
        float2 c[8];
        #pragma unroll
        for (int j = 0; j < 8; j++) c[j] = unpack2(acc2[p][j]);
        #pragma unroll
        for (int half = 0; half < 2; half++) {
            long row = i0 + ty * 8 + 2 * p + half;
            #pragma unroll
            for (int jq = 0; jq < 2; jq++) {
                int col = j0 + tx * 8 + jq * 4;
                float4 v;
                v.x = alpha * (half ? c[jq*4+0].y : c[jq*4+0].x);
                v.y = alpha * (half ? c[jq*4+1].y : c[jq*4+1].x);
                v.z = alpha * (half ? c[jq*4+2].y : c[jq*4+2].x);
                v.w = alpha * (half ? c[jq*4+3].y : c[jq*4+3].x);
                if (bias) {
                    v.x += bias[col + 0]; v.y += bias[col + 1];
                    v.z += bias[col + 2]; v.w += bias[col + 3];
                }
                *(float4*)&C[row * N + col] = v;
            }
        }
    }
}

// ---------------- batched 64x64-tile GEMM, f32x2, high occupancy ----------------
template<int TRANSA>
__global__ __launch_bounds__(256) void gemm64_kernel(
    const float* __restrict__ A, const float* __restrict__ B,
    const float* __restrict__ D, float* __restrict__ C,
    int K, int lda, int ldb, int ldc,
    long sAo, long sAi, long sBo, long sBi, long sDo, long sDi, long sCo, long sCi,
    float alpha, float beta)
{
    int z = blockIdx.z; int zb = z >> 3, zh = z & 7;
    A += zb * sAo + zh * sAi;
    B += zb * sBo + zh * sBi;
    C += zb * sCo + zh * sCi;
    if (D) D += zb * sDo + zh * sDi;

    __shared__ float As[2][8][68];
    __shared__ float Bs[2][8][68];

    int tid = threadIdx.x;
    int ty = tid >> 4, tx = tid & 15;
    int i0 = blockIdx.y * 64, j0 = blockIdx.x * 64;

    bool isA = tid < 128;
    int lt = tid & 127;
    int l_k  = lt >> 4;            // 0..7
    int l_q4 = (lt & 15) * 4;      // 0..60
    int a_row = lt >> 1;           // 0..63 (TRANSA=0)
    int a_kq  = (lt & 1) * 4;      // 0 or 4

    const float* Lptr;
    long lstride;
    if (isA) {
        if (TRANSA) { Lptr = A + (long)l_k * lda + i0 + l_q4; lstride = 8L * lda; }
        else        { Lptr = A + (long)(i0 + a_row) * lda + a_kq; lstride = 8; }
    } else {
        Lptr = B + (long)l_k * ldb + j0 + l_q4; lstride = 8L * ldb;
    }

    float4 lv = *(const float4*)Lptr;
    if (isA) {
        if (TRANSA) *(float4*)&As[0][l_k][l_q4] = lv;
        else {
            As[0][a_kq + 0][a_row] = lv.x; As[0][a_kq + 1][a_row] = lv.y;
            As[0][a_kq + 2][a_row] = lv.z; As[0][a_kq + 3][a_row] = lv.w;
        }
    } else {
        *(float4*)&Bs[0][l_k][l_q4] = lv;
    }
    __syncthreads();

    u64 acc2[2][4] = {};    // 2 row-pairs x 4 cols
    int T = K / 8;
    int buf = 0;
    for (int t = 0; t < T; t++) {
        if (t + 1 < T) lv = *(const float4*)(Lptr + (long)(t + 1) * lstride);
        #pragma unroll
        for (int kk = 0; kk < 8; kk++) {
            ulonglong2 ap = *(const ulonglong2*)&As[buf][kk][ty * 4];
            float4 b0 = *(const float4*)&Bs[buf][kk][tx * 4];
            u64 bd0 = dup2(b0.x), bd1 = dup2(b0.y), bd2 = dup2(b0.z), bd3 = dup2(b0.w);
            ffma2(acc2[0][0], ap.x, bd0); ffma2(acc2[0][1], ap.x, bd1);
            ffma2(acc2[0][2], ap.x, bd2); ffma2(acc2[0][3], ap.x, bd3);
            ffma2(acc2[1][0], ap.y, bd0); ffma2(acc2[1][1], ap.y, bd1);
            ffma2(acc2[1][2], ap.y, bd2); ffma2(acc2[1][3], ap.y, bd3);
        }
        if (t + 1 < T) {
            int nb = buf ^ 1;
            if (isA) {
                if (TRANSA) *(float4*)&As[nb][l_k][l_q4] = lv;
                else {
                    As[nb][a_kq + 0][a_row] = lv.x; As[nb][a_kq + 1][a_row] = lv.y;
                    As[nb][a_kq + 2][a_row] = lv.z; As[nb][a_kq + 3][a_row] = lv.w;
                }
            } else {
                *(float4*)&Bs[nb][l_k][l_q4] = lv;
            }
            __syncthreads();
            buf = nb;
        }
    }

    #pragma unroll
    for (int p = 0; p < 2; p++) {
        float2 c0 = unpack2(acc2[p][0]);
        float2 c1 = unpack2(acc2[p][1]);
        float2 c2 = unpack2(acc2[p][2]);
        float2 c3 = unpack2(acc2[p][3]);
        #pragma unroll
        for (int half = 0; half < 2; half++) {
            long row = i0 + ty * 4 + 2 * p + half;
            long off = row * ldc + j0 + tx * 4;
            float4 v;
            v.x = alpha * (half ? c0.y : c0.x);
            v.y = alpha * (half ? c1.y : c1.x);
            v.z = alpha * (half ? c2.y : c2.x);
            v.w = alpha * (half ? c3.y : c3.x);
            if (D) {
                float4 dv = *(const float4*)&D[off];
                v.x += beta * dv.x; v.y += beta * dv.y;
                v.z += beta * dv.z; v.w += beta * dv.w;
            }
            *(float4*)&C[off] = v;
        }
    }
}

// ---------------- landmark pooling (writes TRANSPOSED klT[bh][d][m]) ----------------
__global__ void landmark_kernel(const float* __restrict__ kv, float* __restrict__ klT)
{
    int dd = threadIdx.x;
    int j  = blockIdx.x;
    int bh = blockIdx.y;
    int b = bh >> 3, h = bh & 7;
    const float* base = kv + (long)b * NN_ * 1024 + (long)(j * 16) * 1024 + h * DHv + dd;
    float s = 0.f;
    #pragma unroll
    for (int t = 0; t < 16; t++) s += base[(long)t * 1024];
    klT[((long)bh * DHv + dd) * LMv + j] = s;
}

// ---------------- row softmax over 256 columns (in place) ----------------
__global__ void softmax256_kernel(float* __restrict__ a)
{
    int row = blockIdx.x * 8 + (threadIdx.x >> 5);
    int lane = threadIdx.x & 31;
    float* p = a + (long)row * 256;
    float v[8];
    float mx = -1e30f;
    #pragma unroll
    for (int t = 0; t < 8; t++) { v[t] = p[lane + 32 * t]; mx = fmaxf(mx, v[t]); }
    #pragma unroll
    for (int o = 16; o > 0; o >>= 1) mx = fmaxf(mx, __shfl_xor_sync(0xffffffffu, mx, o));
    float s = 0.f;
    #pragma unroll
    for (int t = 0; t < 8; t++) { v[t] = __expf(v[t] - mx); s += v[t]; }
    #pragma unroll
    for (int o = 16; o > 0; o >>= 1) s += __shfl_xor_sync(0xffffffffu, s, o);
    float inv = 1.f / s;
    #pragma unroll
    for (int t = 0; t < 8; t++) p[lane + 32 * t] = v[t] * inv;
}

// ---------------- column sums of attn1 + global max ----------------
__global__ void initmax_kernel(float* m) { m[0] = 0.f; }

__global__ void colsummax_kernel(const float* __restrict__ a, float* __restrict__ dmax)
{
    int idx = blockIdx.x * blockDim.x + threadIdx.x;
    int bh = idx >> 8, j = idx & 255;
    const float* p = a + (long)bh * NQv * LMv + j;
    float s = 0.f;
    for (int i = 0; i < NQv; i++) s += p[(long)i * 256];
    atomicMax((int*)dmax, __float_as_int(s));
}

// ---------------- q0 = alpha * I ----------------
__global__ void qinit_kernel(float* __restrict__ q, const float* __restrict__ dmax)
{
    long idx = (long)blockIdx.x * 256 + threadIdx.x;
    int r = (int)((idx >> 8) & 255), c = (int)(idx & 255);
    q[idx] = (r == c) ? (1.0f / dmax[0]) : 0.f;
}

// ---------------- flash attention v5: 128q x 128k tiles, 512 threads, f32x2 -------
// grid (NQ/128, 16), 512 threads (16 warps/SM), smem 169984 B (1 block/SM)
// per-thread: S-tile 4 rows x 8 cols, O-tile 4 rows x 4 cols
#define FLASH2_SMEM ((2*64*132 + 128*68 + 128*132) * 4)
__global__ __launch_bounds__(512) void flash2_kernel(
    const float* __restrict__ qmat, const float* __restrict__ kv, float* __restrict__ Y)
{
    int bh = blockIdx.y; int b = bh >> 3, h = bh & 7;
    const float* qb = qmat + (long)b * NQv * INNER + h * DHv;
    const float* kb = kv + (long)b * NN_ * 1024 + h * DHv;
    const float* vb = kb + 512;
    int i0 = blockIdx.x * 128;

    extern __shared__ float sm[];
    float (*Qts)[132] = (float(*)[132])sm;
    float (*Kts)[132] = (float(*)[132])(sm + 64 * 132);
    float (*Vs)[68]   = (float(*)[68]) (sm + 2 * 64 * 132);
    float (*Ps)[132]  = (float(*)[132])(sm + 2 * 64 * 132 + 128 * 68);

    int tid = threadIdx.x;
    int ty = tid >> 4, tx = tid & 15;   // ty 0..31 (4 rows each), tx 0..15 (8 cols S / 4 cols O)
    int lr = tid >> 4;                   // 0..31
    int ldq = (tid & 15) << 2;           // 0..60

    // Q tile: vector LDG + scalar transpose STS (512 threads, 4 rows each)
    #pragma unroll
    for (int u = 0; u < 4; u++) {
        int r = u * 32 + lr;
        float4 f = *(const float4*)(qb + (long)(i0 + r) * INNER + ldq);
        Qts[ldq + 0][r] = f.x; Qts[ldq + 1][r] = f.y;
        Qts[ldq + 2][r] = f.z; Qts[ldq + 3][r] = f.w;
    }

    float m[4], l[4];
    u64 o2[4][2];
    #pragma unroll
    for (int i = 0; i < 4; i++) {
        m[i] = -1e30f; l[i] = 0.f;
        o2[i][0] = 0ull; o2[i][1] = 0ull;
    }

    for (int c0 = 0; c0 < NN_; c0 += 128) {
        #pragma unroll
        for (int u = 0; u < 4; u++) {
            int r = u * 32 + lr;
            float4 fk = *(const float4*)(kb + (long)(c0 + r) * 1024 + ldq);
            Kts[ldq + 0][r] = fk.x; Kts[ldq + 1][r] = fk.y;
            Kts[ldq + 2][r] = fk.z; Kts[ldq + 3][r] = fk.w;
            float4 fv = *(const float4*)(vb + (long)(c0 + r) * 1024 + ldq);
            *(float4*)&Vs[r][ldq] = fv;
        }
        __syncthreads();

        // S = Q^T K : 2 row-pairs x 8 cols, f32x2
        u64 s2[2][8] = {};
        #pragma unroll
        for (int d = 0; d < 64; d++) {
            ulonglong2 ap2 = *(const ulonglong2*)&Qts[d][ty * 4];
            float4 b0 = *(const float4*)&Kts[d][tx * 8];
            float4 b1 = *(const float4*)&Kts[d][tx * 8 + 4];
            u64 bd[8] = {dup2(b0.x), dup2(b0.y), dup2(b0.z), dup2(b0.w),
                         dup2(b1.x), dup2(b1.y), dup2(b1.z), dup2(b1.w)};
            #pragma unroll
            for (int j = 0; j < 8; j++) {
                ffma2(s2[0][j], ap2.x, bd[j]);
                ffma2(s2[1][j], ap2.y, bd[j]);
            }
        }

        // online softmax per row-pair
        #pragma unroll
        for (int p = 0; p < 2; p++) {
            int r0 = 2 * p, r1 = 2 * p + 1;
            float mx0 = -1e30f, mx1 = -1e30f;
            #pragma unroll
            for (int j = 0; j < 8; j++) {
                float2 f = unpack2(s2[p][j]);
                mx0 = fmaxf(mx0, f.x); mx1 = fmaxf(mx1, f.y);
            }
            #pragma unroll
            for (int off = 8; off > 0; off >>= 1) {
                mx0 = fmaxf(mx0, __shfl_xor_sync(0xffffffffu, mx0, off));
                mx1 = fmaxf(mx1, __shfl_xor_sync(0xffffffffu, mx1, off));
            }
            float mn0 = fmaxf(m[r0], mx0), mn1 = fmaxf(m[r1], mx1);
            float corr0 = __expf(m[r0] - mn0), corr1 = __expf(m[r1] - mn1);
            float rs0 = 0.f, rs1 = 0.f;
            #pragma unroll
            for (int j = 0; j < 8; j++) {
                float2 f = unpack2(s2[p][j]);
                float e0 = __expf(f.x - mn0);
                float e1 = __expf(f.y - mn1);
                rs0 += e0; rs1 += e1;
                Ps[ty * 4 + r0][tx * 8 + j] = e0;
                Ps[ty * 4 + r1][tx * 8 + j] = e1;
            }
            #pragma unroll
            for (int off = 8; off > 0; off >>= 1) {
                rs0 += __shfl_xor_sync(0xffffffffu, rs0, off);
                rs1 += __shfl_xor_sync(0xffffffffu, rs1, off);
            }
            l[r0] = l[r0] * corr0 + rs0;
            l[r1] = l[r1] * corr1 + rs1;
            u64 cd0 = dup2(corr0), cd1 = dup2(corr1);
            fmul2(o2[r0][0], cd0); fmul2(o2[r0][1], cd0);
            fmul2(o2[r1][0], cd1); fmul2(o2[r1][1], cd1);
            m[r0] = mn0; m[r1] = mn1;
        }
        __syncthreads();

        // O += P V : f32x2 (4 rows x 4 cols per thread)
        #pragma unroll 4
        for (int c = 0; c < 128; c += 4) {
            ulonglong2 v0 = *(const ulonglong2*)&Vs[c + 0][tx * 4];
            ulonglong2 v1 = *(const ulonglong2*)&Vs[c + 1][tx * 4];
            ulonglong2 v2 = *(const ulonglong2*)&Vs[c + 2][tx * 4];
            ulonglong2 v3 = *(const ulonglong2*)&Vs[c + 3][tx * 4];
            #pragma unroll
            for (int i = 0; i < 4; i++) {
                float4 p = *(const float4*)&Ps[ty * 4 + i][c];
                u64 pd;
                pd = dup2(p.x); ffma2(o2[i][0], pd, v0.x); ffma2(o2[i][1], pd, v0.y);
                pd = dup2(p.y); ffma2(o2[i][0], pd, v1.x); ffma2(o2[i][1], pd, v1.y);
                pd = dup2(p.z); ffma2(o2[i][0], pd, v2.x); ffma2(o2[i][1], pd, v2.y);
                pd = dup2(p.w); ffma2(o2[i][0], pd, v3.x); ffma2(o2[i][1], pd, v3.y);
            }
        }
        __syncthreads();
    }

    #pragma unroll
    for (int i = 0; i < 4; i++) {
        float inv = 1.f / l[i];
        float2 f0 = unpack2(o2[i][0]);
        float2 f1 = unpack2(o2[i][1]);
        float4 v = make_float4(f0.x * inv, f0.y * inv, f1.x * inv, f1.y * inv);
        *(float4*)&Y[((long)bh * NQv + (i0 + ty * 4 + i)) * DHv + tx * 4] = v;
    }
}

// ---------------- host launch ----------------
static void* sym(const void* s) { void* p = nullptr; cudaGetSymbolAddress(&p, s); return p; }

extern "C" void kernel_launch(void* const* d_in, const int* in_sizes, int n_in,
                              void* d_out, int out_size)
{
    const float* x      = (const float*)d_in[0];
    const float* qin    = (const float*)d_in[1];
    const float* W_kv   = (const float*)d_in[2];
    const float* W_q    = (const float*)d_in[3];
    const float* W_out  = (const float*)d_in[4];
    const float* b_out  = (const float*)d_in[5];
    float* out = (float*)d_out;

    float* kv    = (float*)sym(g_kv);
    float* qmat  = (float*)sym(g_qmat);
    float* klT   = (float*)sym(g_klT);
    float* attn1 = (float*)sym(g_attn1);
    float* G     = (float*)sym(g_G);
    float* qA    = (float*)sym(g_qA);
    float* qB    = (float*)sym(g_qB);
    float* Mb    = (float*)sym(g_M);
    float* r1    = (float*)sym(g_r1);
    float* r2    = (float*)sym(g_r2);
    float* Yb    = (float*)sym(g_Y);
    float* xty   = (float*)sym(g_xty);
    float* z2    = (float*)sym(g_z2);
    float* oc    = (float*)sym(g_oc);
    float* dmax  = (float*)sym(g_max);

    static bool init_done = false;
    static cudaStream_t s1;
    static cudaEvent_t eIn, eKV, eQ, eAttn, eY;
    if (!init_done) {
        cudaFuncSetAttribute(flash2_kernel, cudaFuncAttributeMaxDynamicSharedMemorySize, FLASH2_SMEM);
        cudaStreamCreateWithFlags(&s1, cudaStreamNonBlocking);
        cudaEventCreateWithFlags(&eIn,   cudaEventDisableTiming);
        cudaEventCreateWithFlags(&eKV,   cudaEventDisableTiming);
        cudaEventCreateWithFlags(&eQ,    cudaEventDisableTiming);
        cudaEventCreateWithFlags(&eAttn, cudaEventDisableTiming);
        cudaEventCreateWithFlags(&eY,    cudaEventDisableTiming);
        init_done = true;
    }

    const float scale = 0.125f;
    const long PQ = (long)LMv * LMv;
    const long A1 = (long)NQv * LMv;
    const long YS = (long)NQv * DHv;
    const long XS = (long)LMv * DHv;
    const long KLT = (long)DHv * LMv;

    // fork point
    cudaEventRecord(eIn, 0);
    cudaStreamWaitEvent(s1, eIn, 0);

    // launch #1  s0: kv = x @ W_kv
    sgemm128_kernel<<<dim3(1024/128, 8192/128, 1), 256, 0, 0>>>(
        x, W_kv, nullptr, kv, 8192, 1024, 512, 1.f);
    cudaEventRecord(eKV, 0);

    // launch #2  s1: qmat = scale * (q_input @ W_q)
    sgemm128_kernel<<<dim3(512/128, 2048/128, 1), 256, 0, s1>>>(
        qin, W_q, nullptr, qmat, 2048, 512, 512, scale);
    cudaEventRecord(eQ, s1);

    // launch #3  s0: landmarks (transposed output)
    landmark_kernel<<<dim3(256, 16), 64, 0, 0>>>(kv, klT);

    // launch #4  s1: flash (waits kv) — positioned for ncu profiling
    cudaStreamWaitEvent(s1, eKV, 0);
    flash2_kernel<<<dim3(NQv / 128, 16), 512, FLASH2_SMEM, s1>>>(qmat, kv, Yb);

    // launch #5  s0: sim1 = q @ klT  (needs qmat + landmarks)
    cudaStreamWaitEvent(0, eQ, 0);
    gemm64_kernel<0><<<dim3(4, 16, 16), 256, 0, 0>>>(
        qmat, klT, nullptr, attn1, 64, 512, 256, 256,
        (long)NQv*INNER, 64, 8*KLT, KLT, 0,0, 8*A1, A1, 1.f, 0.f);

    // launch #6  s0: softmax
    softmax256_kernel<<<(BHv * NQv) / 8, 256, 0, 0>>>(attn1);
    cudaEventRecord(eAttn, 0);

    // s1: xty = attn1^T @ Y (after flash; waits attn1)
    cudaStreamWaitEvent(s1, eAttn, 0);
    gemm64_kernel<1><<<dim3(1, 4, 16), 256, 0, s1>>>(
        attn1, Yb, nullptr, xty, 1024, 256, 64, 64,
        8*A1, A1, 8*YS, YS, 0,0, 8*XS, XS, 1.f, 0.f);
    cudaEventRecord(eY, s1);

    // ---- s0 branch: G + alpha + pinv chain ----
    gemm64_kernel<1><<<dim3(4, 4, 16), 256, 0, 0>>>(
        attn1, attn1, nullptr, G, 1024, 256, 256, 256,
        8*A1, A1, 8*A1, A1, 0,0, 8*PQ, PQ, 1.f, 0.f);

    initmax_kernel<<<1, 1, 0, 0>>>(dmax);
    colsummax_kernel<<<16, 256, 0, 0>>>(attn1, dmax);
    qinit_kernel<<<(BHv * 256 * 256) / 256, 256, 0, 0>>>(qA, dmax);

    float* qc = qA; float* qn = qB;
    for (int it = 0; it < 6; it++) {
        gemm64_kernel<0><<<dim3(4, 4, 16), 256, 0, 0>>>(
            qc, G, nullptr, Mb, 256, 256, 256, 256,
            8*PQ, PQ, 8*PQ, PQ, 0,0, 8*PQ, PQ, 1.f, 0.f);
        gemm64_kernel<0><<<dim3(4, 4, 16), 256, 0, 0>>>(
            Mb, qc, qc, r1, 256, 256, 256, 256,
            8*PQ, PQ, 8*PQ, PQ, 8*PQ, PQ, 8*PQ, PQ, -1.f, 7.f);
        gemm64_kernel<0><<<dim3(4, 4, 16), 256, 0, 0>>>(
            Mb, r1, qc, r2, 256, 256, 256, 256,
            8*PQ, PQ, 8*PQ, PQ, 8*PQ, PQ, 8*PQ, PQ, -1.f, 15.f);
        gemm64_kernel<0><<<dim3(4, 4, 16), 256, 0, 0>>>(
            Mb, r2, qc, qn, 256, 256, 256, 256,
            8*PQ, PQ, 8*PQ, PQ, 8*PQ, PQ, 8*PQ, PQ, -0.25f, 3.25f);
        float* t = qc; qc = qn; qn = t;
    }

    // join
    cudaStreamWaitEvent(0, eY, 0);

    gemm64_kernel<0><<<dim3(1, 4, 16), 256, 0, 0>>>(
        qc, xty, nullptr, z2, 256, 256, 64, 64,
        8*PQ, PQ, 8*XS, XS, 0,0, 8*XS, XS, 1.f, 0.f);

    gemm64_kernel<0><<<dim3(1, 16, 16), 256, 0, 0>>>(
        attn1, z2, nullptr, oc, 256, 256, 64, 512,
        8*A1, A1, 8*XS, XS, 0,0, (long)NQv*INNER, 64, 1.f, 0.f);

    sgemm128_kernel<<<dim3(512/128, 2048/128, 1), 256, 0, 0>>>(
        oc, W_out, b_out, out, 2048, 512, 512, 1.f);
}

// round 15
// speedup vs baseline: 1.0869x; 1.0869x over previous
#include <cuda_runtime.h>
#include <cuda_bf16.h>
#include <cstdint>

// Problem constants
#define BB   2
#define NN_  4096
#define NQv  1024
#define DIMv 512
#define HH   8
#define DHv  64
#define LMv  256
#define BHv  16
#define INNER 512

typedef unsigned long long u64;

// ---------------- f32x2 packed helpers (Blackwell) ----------------
__device__ __forceinline__ void ffma2(u64 &d, u64 a, u64 b) {
    asm("fma.rn.f32x2 %0, %1, %2, %0;" : "+l"(d) : "l"(a), "l"(b));
}
__device__ __forceinline__ u64 pack2(float x, float y) {
    u64 r; asm("mov.b64 %0, {%1, %2};" : "=l"(r) : "f"(x), "f"(y)); return r;
}
__device__ __forceinline__ u64 dup2(float x) { return pack2(x, x); }
__device__ __forceinline__ float2 unpack2(u64 v) {
    float lo, hi; asm("mov.b64 {%0, %1}, %2;" : "=f"(lo), "=f"(hi) : "l"(v));
    return make_float2(lo, hi);
}
__device__ __forceinline__ void fmul2(u64 &d, u64 a) {
    asm("mul.rn.f32x2 %0, %0, %1;" : "+l"(d) : "l"(a));
}

// ---------------- scratch (device globals; no allocation allowed) ----------------
__device__ float g_kv[(long)BB*NN_*1024];
__device__ float g_qmat[(long)BB*NQv*INNER];
__device__ float g_klT[BHv*DHv*LMv];           // landmarks TRANSPOSED (bh, 64, 256)
__device__ float g_attn1[(long)BHv*NQv*LMv];
__device__ float g_G[BHv*LMv*LMv];
__device__ float g_qA[BHv*LMv*LMv];
__device__ float g_qB[BHv*LMv*LMv];
__device__ float g_M[BHv*LMv*LMv];
__device__ float g_r1[BHv*LMv*LMv];
__device__ float g_r2[BHv*LMv*LMv];
__device__ float g_Y[BHv*NQv*DHv];
__device__ float g_xty[BHv*LMv*DHv];
__device__ float g_z2[BHv*LMv*DHv];
__device__ float g_oc[(long)BB*NQv*INNER];
__device__ float g_max[1];

// ---------------- 128x128 SGEMM, f32x2 accumulators (big contiguous GEMMs) -------
__global__ __launch_bounds__(256) void sgemm128_kernel(
    const float* __restrict__ A, const float* __restrict__ B,
    const float* __restrict__ bias, float* __restrict__ C,
    int M, int N, int K, float alpha)
{
    __shared__ float As[2][8][132];
    __shared__ float Bs[2][8][128];

    int tid = threadIdx.x;
    int ty = tid >> 4, tx = tid & 15;
    int i0 = blockIdx.y * 128, j0 = blockIdx.x * 128;

    int arow = tid >> 1, akq = (tid & 1) * 4;
    int bkr = tid >> 5, bcq = (tid & 31) * 4;

    const float* Aptr = A + (long)(i0 + arow) * K + akq;
    const float* Bptr = B + (long)bkr * N + j0 + bcq;

    float4 av = *(const float4*)Aptr;
    float4 bv = *(const float4*)Bptr;
    As[0][akq + 0][arow] = av.x; As[0][akq + 1][arow] = av.y;
    As[0][akq + 2][arow] = av.z; As[0][akq + 3][arow] = av.w;
    *(float4*)&Bs[0][bkr][bcq] = bv;
    __syncthreads();

    u64 acc2[4][8] = {};
    int T = K / 8;
    int buf = 0;
    for (int t = 0; t < T; t++) {
        if (t + 1 < T) {
            av = *(const float4*)(Aptr + (t + 1) * 8);
            bv = *(const float4*)(Bptr + (long)(t + 1) * 8 * N);
        }
        #pragma unroll
        for (int kk = 0; kk < 8; kk++) {
            ulonglong2 a01 = *(const ulonglong2*)&As[buf][kk][ty * 8];
            ulonglong2 a23 = *(const ulonglong2*)&As[buf][kk][ty * 8 + 4];
            float4 b0 = *(const float4*)&Bs[buf][kk][tx * 8];
            float4 b1 = *(const float4*)&Bs[buf][kk][tx * 8 + 4];
            u64 ap[4] = {a01.x, a01.y, a23.x, a23.y};
            u64 bd[8] = {dup2(b0.x), dup2(b0.y), dup2(b0.z), dup2(b0.w),
                         dup2(b1.x), dup2(b1.y), dup2(b1.z), dup2(b1.w)};
            #pragma unroll
            for (int p = 0; p < 4; p++)
                #pragma unroll
                for (int j = 0; j < 8; j++)
                    ffma2(acc2[p][j], ap[p], bd[j]);
        }
        if (t + 1 < T) {
            int nb = buf ^ 1;
            As[nb][akq + 0][arow] = av.x; As[nb][akq + 1][arow] = av.y;
            As[nb][akq + 2][arow] = av.z; As[nb][akq + 3][arow] = av.w;
            *(float4*)&Bs[nb][bkr][bcq] = bv;
            __syncthreads();
            buf = nb;
        }
    }

    #pragma unroll
    for (int p = 0; p < 4; p++) {
        float2 c[8];
        #pragma unroll
        for (int j = 0; j < 8; j++) c[j] = unpack2(acc2[p][j]);
        #pragma unroll
        for (int half = 0; half < 2; half++) {
            long row = i0 + ty * 8 + 2 * p + half;
            #pragma unroll
            for (int jq = 0; jq < 2; jq++) {
                int col = j0 + tx * 8 + jq * 4;
                float4 v;
                v.x = alpha * (half ? c[jq*4+0].y : c[jq*4+0].x);
                v.y = alpha * (half ? c[jq*4+1].y : c[jq*4+1].x);
                v.z = alpha * (half ? c[jq*4+2].y : c[jq*4+2].x);
                v.w = alpha * (half ? c[jq*4+3].y : c[jq*4+3].x);
                if (bias) {
                    v.x += bias[col + 0]; v.y += bias[col + 1];
                    v.z += bias[col + 2]; v.w += bias[col + 3];
                }
                *(float4*)&C[row * N + col] = v;
            }
        }
    }
}

// ---------------- batched 64x64-tile GEMM, f32x2, high occupancy ----------------
template<int TRANSA>
__global__ __launch_bounds__(256) void gemm64_kernel(
    const float* __restrict__ A, const float* __restrict__ B,
    const float* __restrict__ D, float* __restrict__ C,
    int K, int lda, int ldb, int ldc,
    long sAo, long sAi, long sBo, long sBi, long sDo, long sDi, long sCo, long sCi,
    float alpha, float beta)
{
    int z = blockIdx.z; int zb = z >> 3, zh = z & 7;
    A += zb * sAo + zh * sAi;
    B += zb * sBo + zh * sBi;
    C += zb * sCo + zh * sCi;
    if (D) D += zb * sDo + zh * sDi;

    __shared__ float As[2][8][68];
    __shared__ float Bs[2][8][68];

    int tid = threadIdx.x;
    int ty = tid >> 4, tx = tid & 15;
    int i0 = blockIdx.y * 64, j0 = blockIdx.x * 64;

    bool isA = tid < 128;
    int lt = tid & 127;
    int l_k  = lt >> 4;
    int l_q4 = (lt & 15) * 4;
    int a_row = lt >> 1;
    int a_kq  = (lt & 1) * 4;

    const float* Lptr;
    long lstride;
    if (isA) {
        if (TRANSA) { Lptr = A + (long)l_k * lda + i0 + l_q4; lstride = 8L * lda; }
        else        { Lptr = A + (long)(i0 + a_row) * lda + a_kq; lstride = 8; }
    } else {
        Lptr = B + (long)l_k * ldb + j0 + l_q4; lstride = 8L * ldb;
    }

    float4 lv = *(const float4*)Lptr;
    if (isA) {
        if (TRANSA) *(float4*)&As[0][l_k][l_q4] = lv;
        else {
            As[0][a_kq + 0][a_row] = lv.x; As[0][a_kq + 1][a_row] = lv.y;
            As[0][a_kq + 2][a_row] = lv.z; As[0][a_kq + 3][a_row] = lv.w;
        }
    } else {
        *(float4*)&Bs[0][l_k][l_q4] = lv;
    }
    __syncthreads();

    u64 acc2[2][4] = {};
    int T = K / 8;
    int buf = 0;
    for (int t = 0; t < T; t++) {
        if (t + 1 < T) lv = *(const float4*)(Lptr + (long)(t + 1) * lstride);
        #pragma unroll
        for (int kk = 0; kk < 8; kk++) {
            ulonglong2 ap = *(const ulonglong2*)&As[buf][kk][ty * 4];
            float4 b0 = *(const float4*)&Bs[buf][kk][tx * 4];
            u64 bd0 = dup2(b0.x), bd1 = dup2(b0.y), bd2 = dup2(b0.z), bd3 = dup2(b0.w);
            ffma2(acc2[0][0], ap.x, bd0); ffma2(acc2[0][1], ap.x, bd1);
            ffma2(acc2[0][2], ap.x, bd2); ffma2(acc2[0][3], ap.x, bd3);
            ffma2(acc2[1][0], ap.y, bd0); ffma2(acc2[1][1], ap.y, bd1);
            ffma2(acc2[1][2], ap.y, bd2); ffma2(acc2[1][3], ap.y, bd3);
        }
        if (t + 1 < T) {
            int nb = buf ^ 1;
            if (isA) {
                if (TRANSA) *(float4*)&As[nb][l_k][l_q4] = lv;
                else {
                    As[nb][a_kq + 0][a_row] = lv.x; As[nb][a_kq + 1][a_row] = lv.y;
                    As[nb][a_kq + 2][a_row] = lv.z; As[nb][a_kq + 3][a_row] = lv.w;
                }
            } else {
                *(float4*)&Bs[nb][l_k][l_q4] = lv;
            }
            __syncthreads();
            buf = nb;
        }
    }

    #pragma unroll
    for (int p = 0; p < 2; p++) {
        float2 c0 = unpack2(acc2[p][0]);
        float2 c1 = unpack2(acc2[p][1]);
        float2 c2 = unpack2(acc2[p][2]);
        float2 c3 = unpack2(acc2[p][3]);
        #pragma unroll
        for (int half = 0; half < 2; half++) {
            long row = i0 + ty * 4 + 2 * p + half;
            long off = row * ldc + j0 + tx * 4;
            float4 v;
            v.x = alpha * (half ? c0.y : c0.x);
            v.y = alpha * (half ? c1.y : c1.x);
            v.z = alpha * (half ? c2.y : c2.x);
            v.w = alpha * (half ? c3.y : c3.x);
            if (D) {
                float4 dv = *(const float4*)&D[off];
                v.x += beta * dv.x; v.y += beta * dv.y;
                v.z += beta * dv.z; v.w += beta * dv.w;
            }
            *(float4*)&C[off] = v;
        }
    }
}

// ---------------- landmark pooling (writes TRANSPOSED klT[bh][d][m]) ----------------
__global__ void landmark_kernel(const float* __restrict__ kv, float* __restrict__ klT)
{
    int dd = threadIdx.x;
    int j  = blockIdx.x;
    int bh = blockIdx.y;
    int b = bh >> 3, h = bh & 7;
    const float* base = kv + (long)b * NN_ * 1024 + (long)(j * 16) * 1024 + h * DHv + dd;
    float s = 0.f;
    #pragma unroll
    for (int t = 0; t < 16; t++) s += base[(long)t * 1024];
    klT[((long)bh * DHv + dd) * LMv + j] = s;
}

// ---------------- row softmax over 256 columns (in place) ----------------
__global__ void softmax256_kernel(float* __restrict__ a)
{
    int row = blockIdx.x * 8 + (threadIdx.x >> 5);
    int lane = threadIdx.x & 31;
    float* p = a + (long)row * 256;
    float v[8];
    float mx = -1e30f;
    #pragma unroll
    for (int t = 0; t < 8; t++) { v[t] = p[lane + 32 * t]; mx = fmaxf(mx, v[t]); }
    #pragma unroll
    for (int o = 16; o > 0; o >>= 1) mx = fmaxf(mx, __shfl_xor_sync(0xffffffffu, mx, o));
    float s = 0.f;
    #pragma unroll
    for (int t = 0; t < 8; t++) { v[t] = __expf(v[t] - mx); s += v[t]; }
    #pragma unroll
    for (int o = 16; o > 0; o >>= 1) s += __shfl_xor_sync(0xffffffffu, s, o);
    float inv = 1.f / s;
    #pragma unroll
    for (int t = 0; t < 8; t++) p[lane + 32 * t] = v[t] * inv;
}

// ---------------- column sums of attn1 + global max ----------------
__global__ void initmax_kernel(float* m) { m[0] = 0.f; }

__global__ void colsummax_kernel(const float* __restrict__ a, float* __restrict__ dmax)
{
    int idx = blockIdx.x * blockDim.x + threadIdx.x;
    int bh = idx >> 8, j = idx & 255;
    const float* p = a + (long)bh * NQv * LMv + j;
    float s = 0.f;
    for (int i = 0; i < NQv; i++) s += p[(long)i * 256];
    atomicMax((int*)dmax, __float_as_int(s));
}

// ---------------- q0 = alpha * I ----------------
__global__ void qinit_kernel(float* __restrict__ q, const float* __restrict__ dmax)
{
    long idx = (long)blockIdx.x * 256 + threadIdx.x;
    int r = (int)((idx >> 8) & 255), c = (int)(idx & 255);
    q[idx] = (r == c) ? (1.0f / dmax[0]) : 0.f;
}

// ---------------- flash attention: 128q x 128k tiles, f32x2, 8x8 S-tile ----------
// grid (NQ/128, nbh), bh = blockIdx.y + bh_base
#define FLASH2_SMEM ((2*64*132 + 128*68 + 128*132) * 4)
__global__ __launch_bounds__(256) void flash2_kernel(
    const float* __restrict__ qmat, const float* __restrict__ kv, float* __restrict__ Y,
    int bh_base)
{
    int bh = blockIdx.y + bh_base; int b = bh >> 3, h = bh & 7;
    const float* qb = qmat + (long)b * NQv * INNER + h * DHv;
    const float* kb = kv + (long)b * NN_ * 1024 + h * DHv;
    const float* vb = kb + 512;
    int i0 = blockIdx.x * 128;

    extern __shared__ float smf[];
    float (*Qts)[132] = (float(*)[132])smf;
    float (*Kts)[132] = (float(*)[132])(smf + 64 * 132);
    float (*Vs)[68]   = (float(*)[68]) (smf + 2 * 64 * 132);
    float (*Ps)[132]  = (float(*)[132])(smf + 2 * 64 * 132 + 128 * 68);

    int tid = threadIdx.x, ty = tid >> 4, tx = tid & 15;
    int lr = tid >> 4;
    int ldq = (tid & 15) << 2;

    #pragma unroll
    for (int u = 0; u < 8; u++) {
        int r = u * 16 + lr;
        float4 f = *(const float4*)(qb + (long)(i0 + r) * INNER + ldq);
        Qts[ldq + 0][r] = f.x; Qts[ldq + 1][r] = f.y;
        Qts[ldq + 2][r] = f.z; Qts[ldq + 3][r] = f.w;
    }

    float m[8], l[8];
    u64 o2[8][2];
    #pragma unroll
    for (int i = 0; i < 8; i++) {
        m[i] = -1e30f; l[i] = 0.f;
        o2[i][0] = 0ull; o2[i][1] = 0ull;
    }

    for (int c0 = 0; c0 < NN_; c0 += 128) {
        #pragma unroll
        for (int u = 0; u < 8; u++) {
            int r = u * 16 + lr;
            float4 fk = *(const float4*)(kb + (long)(c0 + r) * 1024 + ldq);
            Kts[ldq + 0][r] = fk.x; Kts[ldq + 1][r] = fk.y;
            Kts[ldq + 2][r] = fk.z; Kts[ldq + 3][r] = fk.w;
            float4 fv = *(const float4*)(vb + (long)(c0 + r) * 1024 + ldq);
            *(float4*)&Vs[r][ldq] = fv;
        }
        __syncthreads();

        u64 s2[4][8] = {};
        #pragma unroll
        for (int d = 0; d < 64; d++) {
            ulonglong2 a01 = *(const ulonglong2*)&Qts[d][ty * 8];
            ulonglong2 a23 = *(const ulonglong2*)&Qts[d][ty * 8 + 4];
            float4 b0 = *(const float4*)&Kts[d][tx * 8];
            float4 b1 = *(const float4*)&Kts[d][tx * 8 + 4];
            u64 ap[4] = {a01.x, a01.y, a23.x, a23.y};
            u64 bd[8] = {dup2(b0.x), dup2(b0.y), dup2(b0.z), dup2(b0.w),
                         dup2(b1.x), dup2(b1.y), dup2(b1.z), dup2(b1.w)};
            #pragma unroll
            for (int p = 0; p < 4; p++)
                #pragma unroll
                for (int j = 0; j < 8; j++)
                    ffma2(s2[p][j], ap[p], bd[j]);
        }

        #pragma unroll
        for (int p = 0; p < 4; p++) {
            int r0 = 2 * p, r1 = 2 * p + 1;
            float mx0 = -1e30f, mx1 = -1e30f;
            #pragma unroll
            for (int j = 0; j < 8; j++) {
                float2 f = unpack2(s2[p][j]);
                mx0 = fmaxf(mx0, f.x); mx1 = fmaxf(mx1, f.y);
            }
            #pragma unroll
            for (int off = 8; off > 0; off >>= 1) {
                mx0 = fmaxf(mx0, __shfl_xor_sync(0xffffffffu, mx0, off));
                mx1 = fmaxf(mx1, __shfl_xor_sync(0xffffffffu, mx1, off));
            }
            float mn0 = fmaxf(m[r0], mx0), mn1 = fmaxf(m[r1], mx1);
            float corr0 = __expf(m[r0] - mn0), corr1 = __expf(m[r1] - mn1);
            float rs0 = 0.f, rs1 = 0.f;
            #pragma unroll
            for (int j = 0; j < 8; j++) {
                float2 f = unpack2(s2[p][j]);
                float e0 = __expf(f.x - mn0);
                float e1 = __expf(f.y - mn1);
                rs0 += e0; rs1 += e1;
                Ps[ty * 8 + r0][tx * 8 + j] = e0;
                Ps[ty * 8 + r1][tx * 8 + j] = e1;
            }
            #pragma unroll
            for (int off = 8; off > 0; off >>= 1) {
                rs0 += __shfl_xor_sync(0xffffffffu, rs0, off);
                rs1 += __shfl_xor_sync(0xffffffffu, rs1, off);
            }
            l[r0] = l[r0] * corr0 + rs0;
            l[r1] = l[r1] * corr1 + rs1;
            u64 cd0 = dup2(corr0), cd1 = dup2(corr1);
            fmul2(o2[r0][0], cd0); fmul2(o2[r0][1], cd0);
            fmul2(o2[r1][0], cd1); fmul2(o2[r1][1], cd1);
            m[r0] = mn0; m[r1] = mn1;
        }
        __syncthreads();

        #pragma unroll 4
        for (int c = 0; c < 128; c += 4) {
            ulonglong2 v0 = *(const ulonglong2*)&Vs[c + 0][tx * 4];
            ulonglong2 v1 = *(const ulonglong2*)&Vs[c + 1][tx * 4];
            ulonglong2 v2 = *(const ulonglong2*)&Vs[c + 2][tx * 4];
            ulonglong2 v3 = *(const ulonglong2*)&Vs[c + 3][tx * 4];
            #pragma unroll
            for (int i = 0; i < 8; i++) {
                float4 p = *(const float4*)&Ps[ty * 8 + i][c];
                u64 pd;
                pd = dup2(p.x); ffma2(o2[i][0], pd, v0.x); ffma2(o2[i][1], pd, v0.y);
                pd = dup2(p.y); ffma2(o2[i][0], pd, v1.x); ffma2(o2[i][1], pd, v1.y);
                pd = dup2(p.z); ffma2(o2[i][0], pd, v2.x); ffma2(o2[i][1], pd, v2.y);
                pd = dup2(p.w); ffma2(o2[i][0], pd, v3.x); ffma2(o2[i][1], pd, v3.y);
            }
        }
        __syncthreads();
    }

    #pragma unroll
    for (int i = 0; i < 8; i++) {
        float inv = 1.f / l[i];
        float2 f0 = unpack2(o2[i][0]);
        float2 f1 = unpack2(o2[i][1]);
        float4 v = make_float4(f0.x * inv, f0.y * inv, f1.x * inv, f1.y * inv);
        *(float4*)&Y[((long)bh * NQv + (i0 + ty * 8 + i)) * DHv + tx * 4] = v;
    }
}

// ---------------- host launch ----------------
static void* sym(const void* s) { void* p = nullptr; cudaGetSymbolAddress(&p, s); return p; }

extern "C" void kernel_launch(void* const* d_in, const int* in_sizes, int n_in,
                              void* d_out, int out_size)
{
    const float* x      = (const float*)d_in[0];
    const float* qin    = (const float*)d_in[1];
    const float* W_kv   = (const float*)d_in[2];
    const float* W_q    = (const float*)d_in[3];
    const float* W_out  = (const float*)d_in[4];
    const float* b_out  = (const float*)d_in[5];
    float* out = (float*)d_out;

    float* kv    = (float*)sym(g_kv);
    float* qmat  = (float*)sym(g_qmat);
    float* klT   = (float*)sym(g_klT);
    float* attn1 = (float*)sym(g_attn1);
    float* G     = (float*)sym(g_G);
    float* qA    = (float*)sym(g_qA);
    float* qB    = (float*)sym(g_qB);
    float* Mb    = (float*)sym(g_M);
    float* r1    = (float*)sym(g_r1);
    float* r2    = (float*)sym(g_r2);
    float* Yb    = (float*)sym(g_Y);
    float* xty   = (float*)sym(g_xty);
    float* z2    = (float*)sym(g_z2);
    float* oc    = (float*)sym(g_oc);
    float* dmax  = (float*)sym(g_max);

    static bool init_done = false;
    static cudaStream_t s1;
    static cudaEvent_t eIn, eKV0, eKV, eQ, eAttn, eY;
    if (!init_done) {
        cudaFuncSetAttribute(flash2_kernel, cudaFuncAttributeMaxDynamicSharedMemorySize, FLASH2_SMEM);
        cudaStreamCreateWithFlags(&s1, cudaStreamNonBlocking);
        cudaEventCreateWithFlags(&eIn,   cudaEventDisableTiming);
        cudaEventCreateWithFlags(&eKV0,  cudaEventDisableTiming);
        cudaEventCreateWithFlags(&eKV,   cudaEventDisableTiming);
        cudaEventCreateWithFlags(&eQ,    cudaEventDisableTiming);
        cudaEventCreateWithFlags(&eAttn, cudaEventDisableTiming);
        cudaEventCreateWithFlags(&eY,    cudaEventDisableTiming);
        init_done = true;
    }

    const float scale = 0.125f;
    const long PQ = (long)LMv * LMv;
    const long A1 = (long)NQv * LMv;
    const long YS = (long)NQv * DHv;
    const long XS = (long)LMv * DHv;
    const long KLT = (long)DHv * LMv;

    // fork point
    cudaEventRecord(eIn, 0);
    cudaStreamWaitEvent(s1, eIn, 0);

    // s0: kv chunk 0 (batch 0 rows 0..4095)
    sgemm128_kernel<<<dim3(1024/128, 4096/128, 1), 256, 0, 0>>>(
        x, W_kv, nullptr, kv, 4096, 1024, 512, 1.f);
    cudaEventRecord(eKV0, 0);

    // s1: qmat = scale * (q_input @ W_q)
    sgemm128_kernel<<<dim3(512/128, 2048/128, 1), 256, 0, s1>>>(
        qin, W_q, nullptr, qmat, 2048, 512, 512, scale);
    cudaEventRecord(eQ, s1);

    // s0: kv chunk 1 (batch 1 rows 4096..8191)
    sgemm128_kernel<<<dim3(1024/128, 4096/128, 1), 256, 0, 0>>>(
        x + (long)4096 * 512, W_kv, nullptr, kv + (long)4096 * 1024,
        4096, 1024, 512, 1.f);
    cudaEventRecord(eKV, 0);

    // s1: flash batch 0 (bh 0..7) — needs kv chunk 0 only
    cudaStreamWaitEvent(s1, eKV0, 0);
    flash2_kernel<<<dim3(NQv / 128, 8), 256, FLASH2_SMEM, s1>>>(qmat, kv, Yb, 0);

    // s0: landmarks (needs full kv)
    landmark_kernel<<<dim3(256, 16), 64, 0, 0>>>(kv, klT);

    // s1: flash batch 1 (bh 8..15) — needs full kv
    cudaStreamWaitEvent(s1, eKV, 0);
    flash2_kernel<<<dim3(NQv / 128, 8), 256, FLASH2_SMEM, s1>>>(qmat, kv, Yb, 8);

    // s0: sim1 = q @ klT  (needs qmat + landmarks)
    cudaStreamWaitEvent(0, eQ, 0);
    gemm64_kernel<0><<<dim3(4, 16, 16), 256, 0, 0>>>(
        qmat, klT, nullptr, attn1, 64, 512, 256, 256,
        (long)NQv*INNER, 64, 8*KLT, KLT, 0,0, 8*A1, A1, 1.f, 0.f);

    // s0: softmax
    softmax256_kernel<<<(BHv * NQv) / 8, 256, 0, 0>>>(attn1);
    cudaEventRecord(eAttn, 0);

    // s1: xty = attn1^T @ Y (after both flash halves; waits attn1)
    cudaStreamWaitEvent(s1, eAttn, 0);
    gemm64_kernel<1><<<dim3(1, 4, 16), 256, 0, s1>>>(
        attn1, Yb, nullptr, xty, 1024, 256, 64, 64,
        8*A1, A1, 8*YS, YS, 0,0, 8*XS, XS, 1.f, 0.f);
    cudaEventRecord(eY, s1);

    // ---- s0 branch: G + alpha + pinv chain ----
    gemm64_kernel<1><<<dim3(4, 4, 16), 256, 0, 0>>>(
        attn1, attn1, nullptr, G, 1024, 256, 256, 256,
        8*A1, A1, 8*A1, A1, 0,0, 8*PQ, PQ, 1.f, 0.f);

    initmax_kernel<<<1, 1, 0, 0>>>(dmax);
    colsummax_kernel<<<16, 256, 0, 0>>>(attn1, dmax);
    qinit_kernel<<<(BHv * 256 * 256) / 256, 256, 0, 0>>>(qA, dmax);

    float* qc = qA; float* qn = qB;
    for (int it = 0; it < 6; it++) {
        gemm64_kernel<0><<<dim3(4, 4, 16), 256, 0, 0>>>(
            qc, G, nullptr, Mb, 256, 256, 256, 256,
            8*PQ, PQ, 8*PQ, PQ, 0,0, 8*PQ, PQ, 1.f, 0.f);
        gemm64_kernel<0><<<dim3(4, 4, 16), 256, 0, 0>>>(
            Mb, qc, qc, r1, 256, 256, 256, 256,
            8*PQ, PQ, 8*PQ, PQ, 8*PQ, PQ, 8*PQ, PQ, -1.f, 7.f);
        gemm64_kernel<0><<<dim3(4, 4, 16), 256, 0, 0>>>(
            Mb, r1, qc, r2, 256, 256, 256, 256,
            8*PQ, PQ, 8*PQ, PQ, 8*PQ, PQ, 8*PQ, PQ, -1.f, 15.f);
        gemm64_kernel<0><<<dim3(4, 4, 16), 256, 0, 0>>>(
            Mb, r2, qc, qn, 256, 256, 256, 256,
            8*PQ, PQ, 8*PQ, PQ, 8*PQ, PQ, 8*PQ, PQ, -0.25f, 3.25f);
        float* t = qc; qc = qn; qn = t;
    }

    // join
    cudaStreamWaitEvent(0, eY, 0);

    gemm64_kernel<0><<<dim3(1, 4, 16), 256, 0, 0>>>(
        qc, xty, nullptr, z2, 256, 256, 64, 64,
        8*PQ, PQ, 8*XS, XS, 0,0, 8*XS, XS, 1.f, 0.f);

    gemm64_kernel<0><<<dim3(1, 16, 16), 256, 0, 0>>>(
        attn1, z2, nullptr, oc, 256, 256, 64, 512,
        8*A1, A1, 8*XS, XS, 0,0, (long)NQv*INNER, 64, 1.f, 0.f);

    sgemm128_kernel<<<dim3(512/128, 2048/128, 1), 256, 0, 0>>>(
        oc, W_out, b_out, out, 2048, 512, 512, 1.f);
}

// round 16
// speedup vs baseline: 1.1516x; 1.0595x over previous
#include <cuda_runtime.h>
#include <cuda_bf16.h>
#include <cstdint>

// Problem constants
#define BB   2
#define NN_  4096
#define NQv  1024
#define DIMv 512
#define HH   8
#define DHv  64
#define LMv  256
#define BHv  16
#define INNER 512

typedef unsigned long long u64;

// ---------------- f32x2 packed helpers (Blackwell) ----------------
__device__ __forceinline__ void ffma2(u64 &d, u64 a, u64 b) {
    asm("fma.rn.f32x2 %0, %1, %2, %0;" : "+l"(d) : "l"(a), "l"(b));
}
__device__ __forceinline__ u64 pack2(float x, float y) {
    u64 r; asm("mov.b64 %0, {%1, %2};" : "=l"(r) : "f"(x), "f"(y)); return r;
}
__device__ __forceinline__ u64 dup2(float x) { return pack2(x, x); }
__device__ __forceinline__ float2 unpack2(u64 v) {
    float lo, hi; asm("mov.b64 {%0, %1}, %2;" : "=f"(lo), "=f"(hi) : "l"(v));
    return make_float2(lo, hi);
}
__device__ __forceinline__ void fmul2(u64 &d, u64 a) {
    asm("mul.rn.f32x2 %0, %0, %1;" : "+l"(d) : "l"(a));
}

// upper-triangle tile pairs for 4x4 tiling of 256x256 symmetric outputs
__constant__ int c_PI[10] = {0,0,0,0,1,1,1,2,2,3};
__constant__ int c_PJ[10] = {0,1,2,3,1,2,3,2,3,3};

// ---------------- scratch (device globals; no allocation allowed) ----------------
__device__ float g_kv[(long)BB*NN_*1024];
__device__ float g_qmat[(long)BB*NQv*INNER];
__device__ float g_klT[BHv*DHv*LMv];           // landmarks TRANSPOSED (bh, 64, 256)
__device__ float g_attn1[(long)BHv*NQv*LMv];
__device__ float g_G[BHv*LMv*LMv];
__device__ float g_qA[BHv*LMv*LMv];
__device__ float g_qB[BHv*LMv*LMv];
__device__ float g_M[BHv*LMv*LMv];
__device__ float g_r1[BHv*LMv*LMv];
__device__ float g_r2[BHv*LMv*LMv];
__device__ float g_Y[BHv*NQv*DHv];
__device__ float g_xty[BHv*LMv*DHv];
__device__ float g_z2[BHv*LMv*DHv];
__device__ float g_oc[(long)BB*NQv*INNER];
__device__ float g_max[1];

// ---------------- 128x128 SGEMM, f32x2 accumulators (big contiguous GEMMs) -------
__global__ __launch_bounds__(256) void sgemm128_kernel(
    const float* __restrict__ A, const float* __restrict__ B,
    const float* __restrict__ bias, float* __restrict__ C,
    int M, int N, int K, float alpha)
{
    __shared__ float As[2][8][132];
    __shared__ float Bs[2][8][128];

    int tid = threadIdx.x;
    int ty = tid >> 4, tx = tid & 15;
    int i0 = blockIdx.y * 128, j0 = blockIdx.x * 128;

    int arow = tid >> 1, akq = (tid & 1) * 4;
    int bkr = tid >> 5, bcq = (tid & 31) * 4;

    const float* Aptr = A + (long)(i0 + arow) * K + akq;
    const float* Bptr = B + (long)bkr * N + j0 + bcq;

    float4 av = *(const float4*)Aptr;
    float4 bv = *(const float4*)Bptr;
    As[0][akq + 0][arow] = av.x; As[0][akq + 1][arow] = av.y;
    As[0][akq + 2][arow] = av.z; As[0][akq + 3][arow] = av.w;
    *(float4*)&Bs[0][bkr][bcq] = bv;
    __syncthreads();

    u64 acc2[4][8] = {};
    int T = K / 8;
    int buf = 0;
    for (int t = 0; t < T; t++) {
        if (t + 1 < T) {
            av = *(const float4*)(Aptr + (t + 1) * 8);
            bv = *(const float4*)(Bptr + (long)(t + 1) * 8 * N);
        }
        #pragma unroll
        for (int kk = 0; kk < 8; kk++) {
            ulonglong2 a01 = *(const ulonglong2*)&As[buf][kk][ty * 8];
            ulonglong2 a23 = *(const ulonglong2*)&As[buf][kk][ty * 8 + 4];
            float4 b0 = *(const float4*)&Bs[buf][kk][tx * 8];
            float4 b1 = *(const float4*)&Bs[buf][kk][tx * 8 + 4];
            u64 ap[4] = {a01.x, a01.y, a23.x, a23.y};
            u64 bd[8] = {dup2(b0.x), dup2(b0.y), dup2(b0.z), dup2(b0.w),
                         dup2(b1.x), dup2(b1.y), dup2(b1.z), dup2(b1.w)};
            #pragma unroll
            for (int p = 0; p < 4; p++)
                #pragma unroll
                for (int j = 0; j < 8; j++)
                    ffma2(acc2[p][j], ap[p], bd[j]);
        }
        if (t + 1 < T) {
            int nb = buf ^ 1;
            As[nb][akq + 0][arow] = av.x; As[nb][akq + 1][arow] = av.y;
            As[nb][akq + 2][arow] = av.z; As[nb][akq + 3][arow] = av.w;
            *(float4*)&Bs[nb][bkr][bcq] = bv;
            __syncthreads();
            buf = nb;
        }
    }

    #pragma unroll
    for (int p = 0; p < 4; p++) {
        float2 c[8];
        #pragma unroll
        for (int j = 0; j < 8; j++) c[j] = unpack2(acc2[p][j]);
        #pragma unroll
        for (int half = 0; half < 2; half++) {
            long row = i0 + ty * 8 + 2 * p + half;
            #pragma unroll
            for (int jq = 0; jq < 2; jq++) {
                int col = j0 + tx * 8 + jq * 4;
                float4 v;
                v.x = alpha * (half ? c[jq*4+0].y : c[jq*4+0].x);
                v.y = alpha * (half ? c[jq*4+1].y : c[jq*4+1].x);
                v.z = alpha * (half ? c[jq*4+2].y : c[jq*4+2].x);
                v.w = alpha * (half ? c[jq*4+3].y : c[jq*4+3].x);
                if (bias) {
                    v.x += bias[col + 0]; v.y += bias[col + 1];
                    v.z += bias[col + 2]; v.w += bias[col + 3];
                }
                *(float4*)&C[row * N + col] = v;
            }
        }
    }
}

// ---------------- batched 64x64-tile GEMM, f32x2, high occupancy ----------------
template<int TRANSA>
__global__ __launch_bounds__(256) void gemm64_kernel(
    const float* __restrict__ A, const float* __restrict__ B,
    const float* __restrict__ D, float* __restrict__ C,
    int K, int lda, int ldb, int ldc,
    long sAo, long sAi, long sBo, long sBi, long sDo, long sDi, long sCo, long sCi,
    float alpha, float beta)
{
    int z = blockIdx.z; int zb = z >> 3, zh = z & 7;
    A += zb * sAo + zh * sAi;
    B += zb * sBo + zh * sBi;
    C += zb * sCo + zh * sCi;
    if (D) D += zb * sDo + zh * sDi;

    __shared__ float As[2][8][68];
    __shared__ float Bs[2][8][68];

    int tid = threadIdx.x;
    int ty = tid >> 4, tx = tid & 15;
    int i0 = blockIdx.y * 64, j0 = blockIdx.x * 64;

    bool isA = tid < 128;
    int lt = tid & 127;
    int l_k  = lt >> 4;
    int l_q4 = (lt & 15) * 4;
    int a_row = lt >> 1;
    int a_kq  = (lt & 1) * 4;

    const float* Lptr;
    long lstride;
    if (isA) {
        if (TRANSA) { Lptr = A + (long)l_k * lda + i0 + l_q4; lstride = 8L * lda; }
        else        { Lptr = A + (long)(i0 + a_row) * lda + a_kq; lstride = 8; }
    } else {
        Lptr = B + (long)l_k * ldb + j0 + l_q4; lstride = 8L * ldb;
    }

    float4 lv = *(const float4*)Lptr;
    if (isA) {
        if (TRANSA) *(float4*)&As[0][l_k][l_q4] = lv;
        else {
            As[0][a_kq + 0][a_row] = lv.x; As[0][a_kq + 1][a_row] = lv.y;
            As[0][a_kq + 2][a_row] = lv.z; As[0][a_kq + 3][a_row] = lv.w;
        }
    } else {
        *(float4*)&Bs[0][l_k][l_q4] = lv;
    }
    __syncthreads();

    u64 acc2[2][4] = {};
    int T = K / 8;
    int buf = 0;
    for (int t = 0; t < T; t++) {
        if (t + 1 < T) lv = *(const float4*)(Lptr + (long)(t + 1) * lstride);
        #pragma unroll
        for (int kk = 0; kk < 8; kk++) {
            ulonglong2 ap = *(const ulonglong2*)&As[buf][kk][ty * 4];
            float4 b0 = *(const float4*)&Bs[buf][kk][tx * 4];
            u64 bd0 = dup2(b0.x), bd1 = dup2(b0.y), bd2 = dup2(b0.z), bd3 = dup2(b0.w);
            ffma2(acc2[0][0], ap.x, bd0); ffma2(acc2[0][1], ap.x, bd1);
            ffma2(acc2[0][2], ap.x, bd2); ffma2(acc2[0][3], ap.x, bd3);
            ffma2(acc2[1][0], ap.y, bd0); ffma2(acc2[1][1], ap.y, bd1);
            ffma2(acc2[1][2], ap.y, bd2); ffma2(acc2[1][3], ap.y, bd3);
        }
        if (t + 1 < T) {
            int nb = buf ^ 1;
            if (isA) {
                if (TRANSA) *(float4*)&As[nb][l_k][l_q4] = lv;
                else {
                    As[nb][a_kq + 0][a_row] = lv.x; As[nb][a_kq + 1][a_row] = lv.y;
                    As[nb][a_kq + 2][a_row] = lv.z; As[nb][a_kq + 3][a_row] = lv.w;
                }
            } else {
                *(float4*)&Bs[nb][l_k][l_q4] = lv;
            }
            __syncthreads();
            buf = nb;
        }
    }

    #pragma unroll
    for (int p = 0; p < 2; p++) {
        float2 c0 = unpack2(acc2[p][0]);
        float2 c1 = unpack2(acc2[p][1]);
        float2 c2 = unpack2(acc2[p][2]);
        float2 c3 = unpack2(acc2[p][3]);
        #pragma unroll
        for (int half = 0; half < 2; half++) {
            long row = i0 + ty * 4 + 2 * p + half;
            long off = row * ldc + j0 + tx * 4;
            float4 v;
            v.x = alpha * (half ? c0.y : c0.x);
            v.y = alpha * (half ? c1.y : c1.x);
            v.z = alpha * (half ? c2.y : c2.x);
            v.w = alpha * (half ? c3.y : c3.x);
            if (D) {
                float4 dv = *(const float4*)&D[off];
                v.x += beta * dv.x; v.y += beta * dv.y;
                v.z += beta * dv.z; v.w += beta * dv.w;
            }
            *(float4*)&C[off] = v;
        }
    }
}

// ---------------- SYMMETRIC-output batched 64x64-tile GEMM -----------------------
// Output C = alpha*A@B + beta*D is symmetric (A,B commuting polys of symmetric G;
// D symmetric). Computes only upper-triangle tiles (10 of 16) and mirrors the
// off-diagonal tiles. grid (10, 1, nbatch).
template<int TRANSA>
__global__ __launch_bounds__(256) void gemm64sym_kernel(
    const float* __restrict__ A, const float* __restrict__ B,
    const float* __restrict__ D, float* __restrict__ C,
    int K, int lda, int ldb, int ldc,
    long sAo, long sAi, long sBo, long sBi, long sDo, long sDi, long sCo, long sCi,
    float alpha, float beta)
{
    int z = blockIdx.z; int zb = z >> 3, zh = z & 7;
    A += zb * sAo + zh * sAi;
    B += zb * sBo + zh * sBi;
    C += zb * sCo + zh * sCi;
    if (D) D += zb * sDo + zh * sDi;

    __shared__ float As[2][8][68];
    __shared__ float Bs[2][8][68];

    int tid = threadIdx.x;
    int ty = tid >> 4, tx = tid & 15;
    int bi = c_PI[blockIdx.x], bj = c_PJ[blockIdx.x];
    int i0 = bi * 64, j0 = bj * 64;

    bool isA = tid < 128;
    int lt = tid & 127;
    int l_k  = lt >> 4;
    int l_q4 = (lt & 15) * 4;
    int a_row = lt >> 1;
    int a_kq  = (lt & 1) * 4;

    const float* Lptr;
    long lstride;
    if (isA) {
        if (TRANSA) { Lptr = A + (long)l_k * lda + i0 + l_q4; lstride = 8L * lda; }
        else        { Lptr = A + (long)(i0 + a_row) * lda + a_kq; lstride = 8; }
    } else {
        Lptr = B + (long)l_k * ldb + j0 + l_q4; lstride = 8L * ldb;
    }

    float4 lv = *(const float4*)Lptr;
    if (isA) {
        if (TRANSA) *(float4*)&As[0][l_k][l_q4] = lv;
        else {
            As[0][a_kq + 0][a_row] = lv.x; As[0][a_kq + 1][a_row] = lv.y;
            As[0][a_kq + 2][a_row] = lv.z; As[0][a_kq + 3][a_row] = lv.w;
        }
    } else {
        *(float4*)&Bs[0][l_k][l_q4] = lv;
    }
    __syncthreads();

    u64 acc2[2][4] = {};
    int T = K / 8;
    int buf = 0;
    for (int t = 0; t < T; t++) {
        if (t + 1 < T) lv = *(const float4*)(Lptr + (long)(t + 1) * lstride);
        #pragma unroll
        for (int kk = 0; kk < 8; kk++) {
            ulonglong2 ap = *(const ulonglong2*)&As[buf][kk][ty * 4];
            float4 b0 = *(const float4*)&Bs[buf][kk][tx * 4];
            u64 bd0 = dup2(b0.x), bd1 = dup2(b0.y), bd2 = dup2(b0.z), bd3 = dup2(b0.w);
            ffma2(acc2[0][0], ap.x, bd0); ffma2(acc2[0][1], ap.x, bd1);
            ffma2(acc2[0][2], ap.x, bd2); ffma2(acc2[0][3], ap.x, bd3);
            ffma2(acc2[1][0], ap.y, bd0); ffma2(acc2[1][1], ap.y, bd1);
            ffma2(acc2[1][2], ap.y, bd2); ffma2(acc2[1][3], ap.y, bd3);
        }
        if (t + 1 < T) {
            int nb = buf ^ 1;
            if (isA) {
                if (TRANSA) *(float4*)&As[nb][l_k][l_q4] = lv;
                else {
                    As[nb][a_kq + 0][a_row] = lv.x; As[nb][a_kq + 1][a_row] = lv.y;
                    As[nb][a_kq + 2][a_row] = lv.z; As[nb][a_kq + 3][a_row] = lv.w;
                }
            } else {
                *(float4*)&Bs[nb][l_k][l_q4] = lv;
            }
            __syncthreads();
            buf = nb;
        }
    }

    bool mirror = (bi != bj);
    #pragma unroll
    for (int p = 0; p < 2; p++) {
        float2 c0 = unpack2(acc2[p][0]);
        float2 c1 = unpack2(acc2[p][1]);
        float2 c2 = unpack2(acc2[p][2]);
        float2 c3 = unpack2(acc2[p][3]);
        #pragma unroll
        for (int half = 0; half < 2; half++) {
            int rl = ty * 4 + 2 * p + half;     // local row 0..63
            long row = i0 + rl;
            long off = row * ldc + j0 + tx * 4;
            float4 v;
            v.x = alpha * (half ? c0.y : c0.x);
            v.y = alpha * (half ? c1.y : c1.x);
            v.z = alpha * (half ? c2.y : c2.x);
            v.w = alpha * (half ? c3.y : c3.x);
            if (D) {
                float4 dv = *(const float4*)&D[off];
                v.x += beta * dv.x; v.y += beta * dv.y;
                v.z += beta * dv.z; v.w += beta * dv.w;
            }
            *(float4*)&C[off] = v;
            if (mirror) {
                int cl = tx * 4;                // local col 0..63
                C[(long)(j0 + cl + 0) * ldc + i0 + rl] = v.x;
                C[(long)(j0 + cl + 1) * ldc + i0 + rl] = v.y;
                C[(long)(j0 + cl + 2) * ldc + i0 + rl] = v.z;
                C[(long)(j0 + cl + 3) * ldc + i0 + rl] = v.w;
            }
        }
    }
}

// ---------------- landmark pooling (writes TRANSPOSED klT[bh][d][m]) ----------------
__global__ void landmark_kernel(const float* __restrict__ kv, float* __restrict__ klT)
{
    int dd = threadIdx.x;
    int j  = blockIdx.x;
    int bh = blockIdx.y;
    int b = bh >> 3, h = bh & 7;
    const float* base = kv + (long)b * NN_ * 1024 + (long)(j * 16) * 1024 + h * DHv + dd;
    float s = 0.f;
    #pragma unroll
    for (int t = 0; t < 16; t++) s += base[(long)t * 1024];
    klT[((long)bh * DHv + dd) * LMv + j] = s;
}

// ---------------- row softmax over 256 columns (in place) ----------------
__global__ void softmax256_kernel(float* __restrict__ a)
{
    int row = blockIdx.x * 8 + (threadIdx.x >> 5);
    int lane = threadIdx.x & 31;
    float* p = a + (long)row * 256;
    float v[8];
    float mx = -1e30f;
    #pragma unroll
    for (int t = 0; t < 8; t++) { v[t] = p[lane + 32 * t]; mx = fmaxf(mx, v[t]); }
    #pragma unroll
    for (int o = 16; o > 0; o >>= 1) mx = fmaxf(mx, __shfl_xor_sync(0xffffffffu, mx, o));
    float s = 0.f;
    #pragma unroll
    for (int t = 0; t < 8; t++) { v[t] = __expf(v[t] - mx); s += v[t]; }
    #pragma unroll
    for (int o = 16; o > 0; o >>= 1) s += __shfl_xor_sync(0xffffffffu, s, o);
    float inv = 1.f / s;
    #pragma unroll
    for (int t = 0; t < 8; t++) p[lane + 32 * t] = v[t] * inv;
}

// ---------------- column sums of attn1 + global max ----------------
__global__ void initmax_kernel(float* m) { m[0] = 0.f; }

__global__ void colsummax_kernel(const float* __restrict__ a, float* __restrict__ dmax)
{
    int idx = blockIdx.x * blockDim.x + threadIdx.x;
    int bh = idx >> 8, j = idx & 255;
    const float* p = a + (long)bh * NQv * LMv + j;
    float s = 0.f;
    for (int i = 0; i < NQv; i++) s += p[(long)i * 256];
    atomicMax((int*)dmax, __float_as_int(s));
}

// ---------------- q0 = alpha * I ----------------
__global__ void qinit_kernel(float* __restrict__ q, const float* __restrict__ dmax)
{
    long idx = (long)blockIdx.x * 256 + threadIdx.x;
    int r = (int)((idx >> 8) & 255), c = (int)(idx & 255);
    q[idx] = (r == c) ? (1.0f / dmax[0]) : 0.f;
}

// ---------------- flash attention: 128q x 128k tiles, f32x2, 8x8 S-tile ----------
// grid (NQ/128, nbh), bh = blockIdx.y + bh_base
#define FLASH2_SMEM ((2*64*132 + 128*68 + 128*132) * 4)
__global__ __launch_bounds__(256) void flash2_kernel(
    const float* __restrict__ qmat, const float* __restrict__ kv, float* __restrict__ Y,
    int bh_base)
{
    int bh = blockIdx.y + bh_base; int b = bh >> 3, h = bh & 7;
    const float* qb = qmat + (long)b * NQv * INNER + h * DHv;
    const float* kb = kv + (long)b * NN_ * 1024 + h * DHv;
    const float* vb = kb + 512;
    int i0 = blockIdx.x * 128;

    extern __shared__ float smf[];
    float (*Qts)[132] = (float(*)[132])smf;
    float (*Kts)[132] = (float(*)[132])(smf + 64 * 132);
    float (*Vs)[68]   = (float(*)[68]) (smf + 2 * 64 * 132);
    float (*Ps)[132]  = (float(*)[132])(smf + 2 * 64 * 132 + 128 * 68);

    int tid = threadIdx.x, ty = tid >> 4, tx = tid & 15;
    int lr = tid >> 4;
    int ldq = (tid & 15) << 2;

    #pragma unroll
    for (int u = 0; u < 8; u++) {
        int r = u * 16 + lr;
        float4 f = *(const float4*)(qb + (long)(i0 + r) * INNER + ldq);
        Qts[ldq + 0][r] = f.x; Qts[ldq + 1][r] = f.y;
        Qts[ldq + 2][r] = f.z; Qts[ldq + 3][r] = f.w;
    }

    float m[8], l[8];
    u64 o2[8][2];
    #pragma unroll
    for (int i = 0; i < 8; i++) {
        m[i] = -1e30f; l[i] = 0.f;
        o2[i][0] = 0ull; o2[i][1] = 0ull;
    }

    for (int c0 = 0; c0 < NN_; c0 += 128) {
        #pragma unroll
        for (int u = 0; u < 8; u++) {
            int r = u * 16 + lr;
            float4 fk = *(const float4*)(kb + (long)(c0 + r) * 1024 + ldq);
            Kts[ldq + 0][r] = fk.x; Kts[ldq + 1][r] = fk.y;
            Kts[ldq + 2][r] = fk.z; Kts[ldq + 3][r] = fk.w;
            float4 fv = *(const float4*)(vb + (long)(c0 + r) * 1024 + ldq);
            *(float4*)&Vs[r][ldq] = fv;
        }
        __syncthreads();

        u64 s2[4][8] = {};
        #pragma unroll
        for (int d = 0; d < 64; d++) {
            ulonglong2 a01 = *(const ulonglong2*)&Qts[d][ty * 8];
            ulonglong2 a23 = *(const ulonglong2*)&Qts[d][ty * 8 + 4];
            float4 b0 = *(const float4*)&Kts[d][tx * 8];
            float4 b1 = *(const float4*)&Kts[d][tx * 8 + 4];
            u64 ap[4] = {a01.x, a01.y, a23.x, a23.y};
            u64 bd[8] = {dup2(b0.x), dup2(b0.y), dup2(b0.z), dup2(b0.w),
                         dup2(b1.x), dup2(b1.y), dup2(b1.z), dup2(b1.w)};
            #pragma unroll
            for (int p = 0; p < 4; p++)
                #pragma unroll
                for (int j = 0; j < 8; j++)
                    ffma2(s2[p][j], ap[p], bd[j]);
        }

        #pragma unroll
        for (int p = 0; p < 4; p++) {
            int r0 = 2 * p, r1 = 2 * p + 1;
            float mx0 = -1e30f, mx1 = -1e30f;
            #pragma unroll
            for (int j = 0; j < 8; j++) {
                float2 f = unpack2(s2[p][j]);
                mx0 = fmaxf(mx0, f.x); mx1 = fmaxf(mx1, f.y);
            }
            #pragma unroll
            for (int off = 8; off > 0; off >>= 1) {
                mx0 = fmaxf(mx0, __shfl_xor_sync(0xffffffffu, mx0, off));
                mx1 = fmaxf(mx1, __shfl_xor_sync(0xffffffffu, mx1, off));
            }
            float mn0 = fmaxf(m[r0], mx0), mn1 = fmaxf(m[r1], mx1);
            float corr0 = __expf(m[r0] - mn0), corr1 = __expf(m[r1] - mn1);
            float rs0 = 0.f, rs1 = 0.f;
            #pragma unroll
            for (int j = 0; j < 8; j++) {
                float2 f = unpack2(s2[p][j]);
                float e0 = __expf(f.x - mn0);
                float e1 = __expf(f.y - mn1);
                rs0 += e0; rs1 += e1;
                Ps[ty * 8 + r0][tx * 8 + j] = e0;
                Ps[ty * 8 + r1][tx * 8 + j] = e1;
            }
            #pragma unroll
            for (int off = 8; off > 0; off >>= 1) {
                rs0 += __shfl_xor_sync(0xffffffffu, rs0, off);
                rs1 += __shfl_xor_sync(0xffffffffu, rs1, off);
            }
            l[r0] = l[r0] * corr0 + rs0;
            l[r1] = l[r1] * corr1 + rs1;
            u64 cd0 = dup2(corr0), cd1 = dup2(corr1);
            fmul2(o2[r0][0], cd0); fmul2(o2[r0][1], cd0);
            fmul2(o2[r1][0], cd1); fmul2(o2[r1][1], cd1);
            m[r0] = mn0; m[r1] = mn1;
        }
        __syncthreads();

        #pragma unroll 4
        for (int c = 0; c < 128; c += 4) {
            ulonglong2 v0 = *(const ulonglong2*)&Vs[c + 0][tx * 4];
            ulonglong2 v1 = *(const ulonglong2*)&Vs[c + 1][tx * 4];
            ulonglong2 v2 = *(const ulonglong2*)&Vs[c + 2][tx * 4];
            ulonglong2 v3 = *(const ulonglong2*)&Vs[c + 3][tx * 4];
            #pragma unroll
            for (int i = 0; i < 8; i++) {
                float4 p = *(const float4*)&Ps[ty * 8 + i][c];
                u64 pd;
                pd = dup2(p.x); ffma2(o2[i][0], pd, v0.x); ffma2(o2[i][1], pd, v0.y);
                pd = dup2(p.y); ffma2(o2[i][0], pd, v1.x); ffma2(o2[i][1], pd, v1.y);
                pd = dup2(p.z); ffma2(o2[i][0], pd, v2.x); ffma2(o2[i][1], pd, v2.y);
                pd = dup2(p.w); ffma2(o2[i][0], pd, v3.x); ffma2(o2[i][1], pd, v3.y);
            }
        }
        __syncthreads();
    }

    #pragma unroll
    for (int i = 0; i < 8; i++) {
        float inv = 1.f / l[i];
        float2 f0 = unpack2(o2[i][0]);
        float2 f1 = unpack2(o2[i][1]);
        float4 v = make_float4(f0.x * inv, f0.y * inv, f1.x * inv, f1.y * inv);
        *(float4*)&Y[((long)bh * NQv + (i0 + ty * 8 + i)) * DHv + tx * 4] = v;
    }
}

// ---------------- host launch ----------------
static void* sym(const void* s) { void* p = nullptr; cudaGetSymbolAddress(&p, s); return p; }

extern "C" void kernel_launch(void* const* d_in, const int* in_sizes, int n_in,
                              void* d_out, int out_size)
{
    const float* x      = (const float*)d_in[0];
    const float* qin    = (const float*)d_in[1];
    const float* W_kv   = (const float*)d_in[2];
    const float* W_q    = (const float*)d_in[3];
    const float* W_out  = (const float*)d_in[4];
    const float* b_out  = (const float*)d_in[5];
    float* out = (float*)d_out;

    float* kv    = (float*)sym(g_kv);
    float* qmat  = (float*)sym(g_qmat);
    float* klT   = (float*)sym(g_klT);
    float* attn1 = (float*)sym(g_attn1);
    float* G     = (float*)sym(g_G);
    float* qA    = (float*)sym(g_qA);
    float* qB    = (float*)sym(g_qB);
    float* Mb    = (float*)sym(g_M);
    float* r1    = (float*)sym(g_r1);
    float* r2    = (float*)sym(g_r2);
    float* Yb    = (float*)sym(g_Y);
    float* xty   = (float*)sym(g_xty);
    float* z2    = (float*)sym(g_z2);
    float* oc    = (float*)sym(g_oc);
    float* dmax  = (float*)sym(g_max);

    static bool init_done = false;
    static cudaStream_t s1;
    static cudaEvent_t eIn, eKV0, eKV, eQ, eAttn, eY;
    if (!init_done) {
        cudaFuncSetAttribute(flash2_kernel, cudaFuncAttributeMaxDynamicSharedMemorySize, FLASH2_SMEM);
        cudaStreamCreateWithFlags(&s1, cudaStreamNonBlocking);
        cudaEventCreateWithFlags(&eIn,   cudaEventDisableTiming);
        cudaEventCreateWithFlags(&eKV0,  cudaEventDisableTiming);
        cudaEventCreateWithFlags(&eKV,   cudaEventDisableTiming);
        cudaEventCreateWithFlags(&eQ,    cudaEventDisableTiming);
        cudaEventCreateWithFlags(&eAttn, cudaEventDisableTiming);
        cudaEventCreateWithFlags(&eY,    cudaEventDisableTiming);
        init_done = true;
    }

    const float scale = 0.125f;
    const long PQ = (long)LMv * LMv;
    const long A1 = (long)NQv * LMv;
    const long YS = (long)NQv * DHv;
    const long XS = (long)LMv * DHv;
    const long KLT = (long)DHv * LMv;

    // fork point
    cudaEventRecord(eIn, 0);
    cudaStreamWaitEvent(s1, eIn, 0);

    // s0: kv chunk 0 (batch 0 rows 0..4095)
    sgemm128_kernel<<<dim3(1024/128, 4096/128, 1), 256, 0, 0>>>(
        x, W_kv, nullptr, kv, 4096, 1024, 512, 1.f);
    cudaEventRecord(eKV0, 0);

    // s1: qmat = scale * (q_input @ W_q)
    sgemm128_kernel<<<dim3(512/128, 2048/128, 1), 256, 0, s1>>>(
        qin, W_q, nullptr, qmat, 2048, 512, 512, scale);
    cudaEventRecord(eQ, s1);

    // s0: kv chunk 1 (batch 1 rows 4096..8191)
    sgemm128_kernel<<<dim3(1024/128, 4096/128, 1), 256, 0, 0>>>(
        x + (long)4096 * 512, W_kv, nullptr, kv + (long)4096 * 1024,
        4096, 1024, 512, 1.f);
    cudaEventRecord(eKV, 0);

    // s1: flash batch 0 (bh 0..7)
    cudaStreamWaitEvent(s1, eKV0, 0);
    flash2_kernel<<<dim3(NQv / 128, 8), 256, FLASH2_SMEM, s1>>>(qmat, kv, Yb, 0);

    // s0: landmarks (needs full kv)
    landmark_kernel<<<dim3(256, 16), 64, 0, 0>>>(kv, klT);

    // s1: flash batch 1 (bh 8..15)
    cudaStreamWaitEvent(s1, eKV, 0);
    flash2_kernel<<<dim3(NQv / 128, 8), 256, FLASH2_SMEM, s1>>>(qmat, kv, Yb, 8);

    // s0: sim1 = q @ klT
    cudaStreamWaitEvent(0, eQ, 0);
    gemm64_kernel<0><<<dim3(4, 16, 16), 256, 0, 0>>>(
        qmat, klT, nullptr, attn1, 64, 512, 256, 256,
        (long)NQv*INNER, 64, 8*KLT, KLT, 0,0, 8*A1, A1, 1.f, 0.f);

    // s0: softmax
    softmax256_kernel<<<(BHv * NQv) / 8, 256, 0, 0>>>(attn1);
    cudaEventRecord(eAttn, 0);

    // s1: xty = attn1^T @ Y
    cudaStreamWaitEvent(s1, eAttn, 0);
    gemm64_kernel<1><<<dim3(1, 4, 16), 256, 0, s1>>>(
        attn1, Yb, nullptr, xty, 1024, 256, 64, 64,
        8*A1, A1, 8*YS, YS, 0,0, 8*XS, XS, 1.f, 0.f);
    cudaEventRecord(eY, s1);

    // ---- s0 branch: G + alpha + pinv chain (symmetric-output GEMMs) ----
    gemm64sym_kernel<1><<<dim3(10, 1, 16), 256, 0, 0>>>(
        attn1, attn1, nullptr, G, 1024, 256, 256, 256,
        8*A1, A1, 8*A1, A1, 0,0, 8*PQ, PQ, 1.f, 0.f);

    initmax_kernel<<<1, 1, 0, 0>>>(dmax);
    colsummax_kernel<<<16, 256, 0, 0>>>(attn1, dmax);
    qinit_kernel<<<(BHv * 256 * 256) / 256, 256, 0, 0>>>(qA, dmax);

    float* qc = qA; float* qn = qB;
    for (int it = 0; it < 6; it++) {
        gemm64sym_kernel<0><<<dim3(10, 1, 16), 256, 0, 0>>>(
            qc, G, nullptr, Mb, 256, 256, 256, 256,
            8*PQ, PQ, 8*PQ, PQ, 0,0, 8*PQ, PQ, 1.f, 0.f);
        gemm64sym_kernel<0><<<dim3(10, 1, 16), 256, 0, 0>>>(
            Mb, qc, qc, r1, 256, 256, 256, 256,
            8*PQ, PQ, 8*PQ, PQ, 8*PQ, PQ, 8*PQ, PQ, -1.f, 7.f);
        gemm64sym_kernel<0><<<dim3(10, 1, 16), 256, 0, 0>>>(
            Mb, r1, qc, r2, 256, 256, 256, 256,
            8*PQ, PQ, 8*PQ, PQ, 8*PQ, PQ, 8*PQ, PQ, -1.f, 15.f);
        gemm64sym_kernel<0><<<dim3(10, 1, 16), 256, 0, 0>>>(
            Mb, r2, qc, qn, 256, 256, 256, 256,
            8*PQ, PQ, 8*PQ, PQ, 8*PQ, PQ, 8*PQ, PQ, -0.25f, 3.25f);
        float* t = qc; qc = qn; qn = t;
    }

    // join
    cudaStreamWaitEvent(0, eY, 0);

    gemm64_kernel<0><<<dim3(1, 4, 16), 256, 0, 0>>>(
        qc, xty, nullptr, z2, 256, 256, 64, 64,
        8*PQ, PQ, 8*XS, XS, 0,0, 8*XS, XS, 1.f, 0.f);

    gemm64_kernel<0><<<dim3(1, 16, 16), 256, 0, 0>>>(
        attn1, z2, nullptr, oc, 256, 256, 64, 512,
        8*A1, A1, 8*XS, XS, 0,0, (long)NQv*INNER, 64, 1.f, 0.f);

    sgemm128_kernel<<<dim3(512/128, 2048/128, 1), 256, 0, 0>>>(
        oc, W_out, b_out, out, 2048, 512, 512, 1.f);
}